// round 3
// baseline (speedup 1.0000x reference)
#include <cuda_runtime.h>

#define Bn 16
#define Cn 64
#define Hn 256
#define Wn 256
#define PHn 128
#define PWn 128
#define CH_STRIDE (Hn * Wn)      // 65536 floats between channels (feature)

// ---------------------------------------------------------------------------
// Fully fused kernel: per block = 32x32 output tile (16x16 quads).
// For each 8-channel chunk:
//   1. compute the 18x18 pooled halo tile directly from feature (smem),
//      (avg_pool2d k=3 s=2 pad=1, count_include_pad -> always /9,
//       circular wrap across image edges from jnp.roll)
//   2. accumulate P2 = sum_c pooled^2 over the halo tile,
//   3. per 2x2 quad: accumulate F2 and the 8 cross-products <f, p_s>.
// Final: out = max_s ( F2 - 2*<f,p_s> + P2_s ).
// Pooling warms L1 with exactly the feature lines the quad loads reuse.
// ---------------------------------------------------------------------------
__global__ __launch_bounds__(256, 3) void fused_kernel(const float* __restrict__ feat,
                                                       float* __restrict__ out) {
    __shared__ float sp[8 * 324];    // 8 channels x 18x18 pooled halo = 10,368 B
    __shared__ float sP2[324];       // running sum_c pooled^2 over halo tile

    int b   = blockIdx.z;
    int ph0 = blockIdx.y << 4;       // pooled-tile origin (16x16 interior)
    int pw0 = blockIdx.x << 4;
    int tid = threadIdx.x;
    int qx  = tid & 15, qy = tid >> 4;
    int ph  = ph0 + qy, pw = pw0 + qx;

    float F2a = 0.f, F2b = 0.f, F2c = 0.f, F2d = 0.f;
    float cr[4][8];
#pragma unroll
    for (int i = 0; i < 4; i++)
#pragma unroll
        for (int s = 0; s < 8; s++) cr[i][s] = 0.f;

    const float* fimg  = feat + (size_t)b * Cn * CH_STRIDE;
    const float* fbase = fimg + (ph << 1) * Wn + (pw << 1);
    int sbase = (qy + 1) * 18 + (qx + 1);
    const float inv9 = 1.0f / 9.0f;

    for (int cc = 0; cc < Cn; cc += 8) {
        __syncthreads();   // protect smem reuse across chunks

        // ---- stage 8 channels of the 18x18 pooled halo (computed on the fly)
        for (int k = tid; k < 8 * 324; k += 256) {
            int c = k / 324;
            int r = k - c * 324;
            int i = r / 18;
            int j = r - i * 18;
            int gr = (ph0 - 1 + i) & 127;      // wrapped pooled row
            int gc = (pw0 - 1 + j) & 127;      // wrapped pooled col
            const float* src = fimg + (size_t)(cc + c) * CH_STRIDE;
            int fr = 2 * gr - 1;               // -1..253
            int fc = 2 * gc - 1;               // -1..253
            float s = 0.f;
#pragma unroll
            for (int rr = 0; rr < 3; rr++) {
                int rrow = fr + rr;
                if (rrow < 0) continue;        // zero pad (top); never OOB high
                const float* row = src + rrow * Wn;
                float a0 = (fc >= 0) ? row[fc] : 0.f;   // zero pad (left)
                s += a0 + row[fc + 1] + row[fc + 2];
            }
            sp[k] = s * inv9;
        }
        __syncthreads();

        // ---- fold P2 accumulation over the staged tile
        for (int r = tid; r < 324; r += 256) {
            float acc = (cc == 0) ? 0.f : sP2[r];
#pragma unroll
            for (int c = 0; c < 8; c++) {
                float v = sp[c * 324 + r];
                acc += v * v;
            }
            sP2[r] = acc;
        }

        // ---- quad accumulation: 2 groups of 4 channels, loads front-batched
#pragma unroll
        for (int g = 0; g < 2; g++) {
            float2 fa[4], fb[4];
            const float* fp = fbase + (size_t)(cc + g * 4) * CH_STRIDE;
#pragma unroll
            for (int t = 0; t < 4; t++) {
                fa[t] = *reinterpret_cast<const float2*>(fp);        // L1 hot
                fb[t] = *reinterpret_cast<const float2*>(fp + Wn);
                fp += CH_STRIDE;
            }
#pragma unroll
            for (int t = 0; t < 4; t++) {
                const float* spc = sp + (g * 4 + t) * 324;
                float ps[8];
                ps[0] = spc[sbase - 19]; ps[1] = spc[sbase - 18]; ps[2] = spc[sbase - 17];
                ps[3] = spc[sbase - 1];                           ps[4] = spc[sbase + 1];
                ps[5] = spc[sbase + 17]; ps[6] = spc[sbase + 18]; ps[7] = spc[sbase + 19];

                float f0 = fa[t].x, f1 = fa[t].y, f2 = fb[t].x, f3 = fb[t].y;
                F2a += f0 * f0; F2b += f1 * f1; F2c += f2 * f2; F2d += f3 * f3;
#pragma unroll
                for (int s = 0; s < 8; s++) {
                    cr[0][s] += f0 * ps[s];
                    cr[1][s] += f1 * ps[s];
                    cr[2][s] += f2 * ps[s];
                    cr[3][s] += f3 * ps[s];
                }
            }
        }
    }
    __syncthreads();   // sP2 fully accumulated and visible

    // ---- P2 at the 8 neighbors from the smem tile
    float P2n[8];
    P2n[0] = sP2[sbase - 19]; P2n[1] = sP2[sbase - 18]; P2n[2] = sP2[sbase - 17];
    P2n[3] = sP2[sbase - 1];                             P2n[4] = sP2[sbase + 1];
    P2n[5] = sP2[sbase + 17]; P2n[6] = sP2[sbase + 18]; P2n[7] = sP2[sbase + 19];

    float F2arr[4] = {F2a, F2b, F2c, F2d};
    float res[4];
#pragma unroll
    for (int i = 0; i < 4; i++) {
        float m = -3.4e38f;
#pragma unroll
        for (int s = 0; s < 8; s++) {
            float v = F2arr[i] - 2.f * cr[i][s] + P2n[s];
            m = fmaxf(m, v);
        }
        res[i] = m;
    }

    float* orow = out + (size_t)b * (Hn * Wn) + (ph << 1) * Wn + (pw << 1);
    *reinterpret_cast<float2*>(orow)      = make_float2(res[0], res[1]);
    *reinterpret_cast<float2*>(orow + Wn) = make_float2(res[2], res[3]);
}

// ---------------------------------------------------------------------------
extern "C" void kernel_launch(void* const* d_in, const int* in_sizes, int n_in,
                              void* d_out, int out_size) {
    const float* feat = (const float*)d_in[0];
    float* out = (float*)d_out;
    // dist is fixed at 1 by the problem's setup_inputs (d = 2)

    dim3 g(8, 8, Bn);
    fused_kernel<<<g, 256>>>(feat, out);
}

// round 4
// speedup vs baseline: 1.8584x; 1.8584x over previous
#include <cuda_runtime.h>

#define Bn 16
#define Cn 64
#define Hn 256
#define Wn 256
#define PHn 128
#define PWn 128
#define CH_STRIDE (Hn * Wn)      // 65536 floats between channels (feature)
#define PCH_STRIDE (PHn * PWn)   // 16384 floats between channels (pooled)

typedef unsigned long long u64;

// scratch (static __device__ — allocation-free per harness rules)
__device__ float g_pooled[Bn * Cn * PHn * PWn];  // 64 MiB

// ---- f32x2 helpers -------------------------------------------------------
__device__ __forceinline__ void fma2(u64& d, u64 a, u64 b) {
    asm("fma.rn.f32x2 %0, %1, %2, %0;" : "+l"(d) : "l"(a), "l"(b));
}
__device__ __forceinline__ u64 bcast2(float v) {
    u64 r;
    asm("mov.b64 %0, {%1, %2};" : "=l"(r) : "f"(v), "f"(v));
    return r;
}
__device__ __forceinline__ float2 unpack2(u64 v) {
    float2 r;
    asm("mov.b64 {%0, %1}, %2;" : "=f"(r.x), "=f"(r.y) : "l"(v));
    return r;
}
__device__ __forceinline__ u64 as_u64(float2 v) {
    u64 r;
    asm("mov.b64 %0, {%1, %2};" : "=l"(r) : "f"(v.x), "f"(v.y));
    return r;
}

// ---- cp.async helpers ----------------------------------------------------
__device__ __forceinline__ void cp_async4(unsigned int smem_dst, const float* src) {
    asm volatile("cp.async.ca.shared.global [%0], [%1], 4;" :: "r"(smem_dst), "l"(src));
}
__device__ __forceinline__ void cp_commit() { asm volatile("cp.async.commit_group;"); }
__device__ __forceinline__ void cp_wait_all() { asm volatile("cp.async.wait_group 0;"); }

// ---------------------------------------------------------------------------
// Pass 1: avg_pool2d k=3 s=2 pad=1 (count_include_pad: always /9).
// 84% DRAM — near roofline; unchanged.
// ---------------------------------------------------------------------------
__global__ __launch_bounds__(256) void pool_kernel(const float* __restrict__ feat) {
    int idx = blockIdx.x * 256 + threadIdx.x;
    int pwq = idx & 31;
    int t   = idx >> 5;
    int ph  = t & 127;
    int bc  = t >> 7;
    const float* src = feat + (size_t)bc * (Hn * Wn);
    int c0 = pwq << 3;

    float s0 = 0.f, s1 = 0.f, s2 = 0.f, s3 = 0.f;
    int rbase = 2 * ph - 1;
#pragma unroll
    for (int rr = 0; rr < 3; rr++) {
        int r = rbase + rr;
        if (r < 0) continue;
        const float* row = src + r * Wn;
        float left = (c0 > 0) ? __ldcs(row + c0 - 1) : 0.f;
        float4 a  = __ldcs(reinterpret_cast<const float4*>(row + c0));
        float4 b4 = __ldcs(reinterpret_cast<const float4*>(row + c0 + 4));
        s0 += left + a.x  + a.y;
        s1 += a.y  + a.z  + a.w;
        s2 += a.w  + b4.x + b4.y;
        s3 += b4.y + b4.z + b4.w;
    }
    const float inv9 = 1.0f / 9.0f;
    float4 o = make_float4(s0 * inv9, s1 * inv9, s2 * inv9, s3 * inv9);
    *reinterpret_cast<float4*>(g_pooled + (size_t)bc * PCH_STRIDE + ph * PWn + (pwq << 2)) = o;
}

// ---------------------------------------------------------------------------
// Pass 2: diff + fused P2. Block = 16x16 quads = 32x32 output tile.
// Pooled halo (18x18) staged per 8-channel chunk via cp.async, double-buffered
// so staging of chunk i+1 overlaps compute of chunk i.
// Math in f32x2 packed pairs (pixel 0/1 and pixel 2/3 of each quad).
// ---------------------------------------------------------------------------
#define CHUNK 8
#define HALO  324   // 18*18

__global__ __launch_bounds__(256, 3) void diff_kernel(const float* __restrict__ feat,
                                                      float* __restrict__ out) {
    __shared__ float sp[2][CHUNK * HALO];  // 2 x 10,368 B
    __shared__ float sP2[HALO];

    int b   = blockIdx.z;
    int ph0 = blockIdx.y << 4;
    int pw0 = blockIdx.x << 4;
    int tid = threadIdx.x;
    int qx  = tid & 15, qy = tid >> 4;
    int ph  = ph0 + qy, pw = pw0 + qx;

    const float* fimg  = feat + (size_t)b * Cn * CH_STRIDE;
    const float* pimg  = g_pooled + (size_t)b * Cn * PCH_STRIDE;
    const float* fbase = fimg + (ph << 1) * Wn + (pw << 1);
    int sbase = (qy + 1) * 18 + (qx + 1);

    unsigned int sp_smem = (unsigned int)__cvta_generic_to_shared(&sp[0][0]);

    // ---- staging lambda: issue cp.async for one 8-channel halo chunk
    auto stage = [&](int buf, int cc) {
        unsigned int dst0 = sp_smem + buf * (CHUNK * HALO * 4);
#pragma unroll 1
        for (int k = tid; k < CHUNK * HALO; k += 256) {
            int c = k / HALO;
            int r = k - c * HALO;
            int i = r / 18;
            int j = r - i * 18;
            int gr = (ph0 - 1 + i) & 127;
            int gc = (pw0 - 1 + j) & 127;
            cp_async4(dst0 + k * 4, pimg + ((size_t)(cc + c) << 14) + (gr << 7) + gc);
        }
        cp_commit();
    };

    u64 z = 0;
    u64 cr01[8], cr23[8];
#pragma unroll
    for (int s = 0; s < 8; s++) { cr01[s] = z; cr23[s] = z; }
    u64 F2_01 = z, F2_23 = z;

    stage(0, 0);

    for (int it = 0; it < Cn / CHUNK; it++) {
        int cur = it & 1;
        cp_wait_all();
        __syncthreads();                       // staged data visible; prev compute done
        if (it + 1 < Cn / CHUNK) stage(1 - cur, (it + 1) * CHUNK);

        const float* spbuf = &sp[cur][0];

        // ---- fold P2 over the staged tile (thread-owned cells)
        for (int r = tid; r < HALO; r += 256) {
            float acc = (it == 0) ? 0.f : sP2[r];
#pragma unroll
            for (int c = 0; c < CHUNK; c++) {
                float v = spbuf[c * HALO + r];
                acc += v * v;
            }
            sP2[r] = acc;
        }

        // ---- quad accumulation: 2 groups of 4 channels, loads front-batched
#pragma unroll
        for (int g = 0; g < 2; g++) {
            float2 fa[4], fb[4];
            const float* fp = fbase + (size_t)(it * CHUNK + g * 4) * CH_STRIDE;
#pragma unroll
            for (int t = 0; t < 4; t++) {
                fa[t] = __ldcs(reinterpret_cast<const float2*>(fp));
                fb[t] = __ldcs(reinterpret_cast<const float2*>(fp + Wn));
                fp += CH_STRIDE;
            }
#pragma unroll
            for (int t = 0; t < 4; t++) {
                const float* spc = spbuf + (g * 4 + t) * HALO;
                float ps[8];
                ps[0] = spc[sbase - 19]; ps[1] = spc[sbase - 18]; ps[2] = spc[sbase - 17];
                ps[3] = spc[sbase - 1];                           ps[4] = spc[sbase + 1];
                ps[5] = spc[sbase + 17]; ps[6] = spc[sbase + 18]; ps[7] = spc[sbase + 19];

                u64 f01 = as_u64(fa[t]);
                u64 f23 = as_u64(fb[t]);
                fma2(F2_01, f01, f01);
                fma2(F2_23, f23, f23);
#pragma unroll
                for (int s = 0; s < 8; s++) {
                    u64 pp = bcast2(ps[s]);
                    fma2(cr01[s], f01, pp);
                    fma2(cr23[s], f23, pp);
                }
            }
        }
    }
    __syncthreads();   // sP2 fully accumulated and visible

    // ---- P2 at the 8 neighbors from the smem tile
    float P2n[8];
    P2n[0] = sP2[sbase - 19]; P2n[1] = sP2[sbase - 18]; P2n[2] = sP2[sbase - 17];
    P2n[3] = sP2[sbase - 1];                             P2n[4] = sP2[sbase + 1];
    P2n[5] = sP2[sbase + 17]; P2n[6] = sP2[sbase + 18]; P2n[7] = sP2[sbase + 19];

    float2 F2p01 = unpack2(F2_01);
    float2 F2p23 = unpack2(F2_23);
    float F2arr[4] = {F2p01.x, F2p01.y, F2p23.x, F2p23.y};

    float res[4] = {-3.4e38f, -3.4e38f, -3.4e38f, -3.4e38f};
#pragma unroll
    for (int s = 0; s < 8; s++) {
        float2 c01 = unpack2(cr01[s]);
        float2 c23 = unpack2(cr23[s]);
        res[0] = fmaxf(res[0], F2arr[0] - 2.f * c01.x + P2n[s]);
        res[1] = fmaxf(res[1], F2arr[1] - 2.f * c01.y + P2n[s]);
        res[2] = fmaxf(res[2], F2arr[2] - 2.f * c23.x + P2n[s]);
        res[3] = fmaxf(res[3], F2arr[3] - 2.f * c23.y + P2n[s]);
    }

    float* orow = out + (size_t)b * (Hn * Wn) + (ph << 1) * Wn + (pw << 1);
    *reinterpret_cast<float2*>(orow)      = make_float2(res[0], res[1]);
    *reinterpret_cast<float2*>(orow + Wn) = make_float2(res[2], res[3]);
}

// ---------------------------------------------------------------------------
extern "C" void kernel_launch(void* const* d_in, const int* in_sizes, int n_in,
                              void* d_out, int out_size) {
    const float* feat = (const float*)d_in[0];
    float* out = (float*)d_out;
    // dist is fixed at 1 by the problem's setup_inputs (d = 2)

    pool_kernel<<<16384, 256>>>(feat);
    dim3 g(8, 8, Bn);
    diff_kernel<<<g, 256>>>(feat, out);
}

// round 5
// speedup vs baseline: 2.0581x; 1.1074x over previous
#include <cuda_runtime.h>

#define Bn 16
#define Cn 64
#define Hn 256
#define Wn 256
#define PHn 128
#define PWn 128
#define CH_STRIDE (Hn * Wn)      // 65536 floats between channels (feature)
#define PCH_STRIDE (PHn * PWn)   // 16384 floats between channels (pooled)

typedef unsigned long long u64;

// scratch (static __device__ — allocation-free per harness rules)
__device__ float g_pooled[Bn * Cn * PHn * PWn];  // 64 MiB

// ---- f32x2 helpers -------------------------------------------------------
__device__ __forceinline__ void fma2(u64& d, u64 a, u64 b) {
    asm("fma.rn.f32x2 %0, %1, %2, %0;" : "+l"(d) : "l"(a), "l"(b));
}
__device__ __forceinline__ u64 bcast2(float v) {
    u64 r;
    asm("mov.b64 %0, {%1, %2};" : "=l"(r) : "f"(v), "f"(v));
    return r;
}
__device__ __forceinline__ float2 unpack2(u64 v) {
    float2 r;
    asm("mov.b64 {%0, %1}, %2;" : "=f"(r.x), "=f"(r.y) : "l"(v));
    return r;
}
__device__ __forceinline__ u64 as_u64(float2 v) {
    u64 r;
    asm("mov.b64 %0, {%1, %2};" : "=l"(r) : "f"(v.x), "f"(v.y));
    return r;
}

// ---- cp.async helpers ----------------------------------------------------
__device__ __forceinline__ void cp_async4(unsigned int smem_dst, const float* src) {
    asm volatile("cp.async.ca.shared.global [%0], [%1], 4;" :: "r"(smem_dst), "l"(src));
}
__device__ __forceinline__ void cp_async16(unsigned int smem_dst, const float* src) {
    asm volatile("cp.async.cg.shared.global [%0], [%1], 16;" :: "r"(smem_dst), "l"(src));
}
__device__ __forceinline__ void cp_commit()  { asm volatile("cp.async.commit_group;"); }
__device__ __forceinline__ void cp_wait1()   { asm volatile("cp.async.wait_group 1;"); }
__device__ __forceinline__ void cp_wait0()   { asm volatile("cp.async.wait_group 0;"); }

// ---------------------------------------------------------------------------
// Pass 1: avg_pool2d k=3 s=2 pad=1 (count_include_pad: always /9).
// 84% DRAM — near roofline; unchanged.
// ---------------------------------------------------------------------------
__global__ __launch_bounds__(256) void pool_kernel(const float* __restrict__ feat) {
    int idx = blockIdx.x * 256 + threadIdx.x;
    int pwq = idx & 31;
    int t   = idx >> 5;
    int ph  = t & 127;
    int bc  = t >> 7;
    const float* src = feat + (size_t)bc * (Hn * Wn);
    int c0 = pwq << 3;

    float s0 = 0.f, s1 = 0.f, s2 = 0.f, s3 = 0.f;
    int rbase = 2 * ph - 1;
#pragma unroll
    for (int rr = 0; rr < 3; rr++) {
        int r = rbase + rr;
        if (r < 0) continue;
        const float* row = src + r * Wn;
        float left = (c0 > 0) ? __ldcs(row + c0 - 1) : 0.f;
        float4 a  = __ldcs(reinterpret_cast<const float4*>(row + c0));
        float4 b4 = __ldcs(reinterpret_cast<const float4*>(row + c0 + 4));
        s0 += left + a.x  + a.y;
        s1 += a.y  + a.z  + a.w;
        s2 += a.w  + b4.x + b4.y;
        s3 += b4.y + b4.z + b4.w;
    }
    const float inv9 = 1.0f / 9.0f;
    float4 o = make_float4(s0 * inv9, s1 * inv9, s2 * inv9, s3 * inv9);
    *reinterpret_cast<float4*>(g_pooled + (size_t)bc * PCH_STRIDE + ph * PWn + (pwq << 2)) = o;
}

// ---------------------------------------------------------------------------
// Pass 2: diff + fused P2. Block = 16x16 quads = 32x32 output tile.
// BOTH the pooled halo (18x18) AND the 32x32 feature tile are staged per
// 4-channel chunk via cp.async, double-buffered. The hot loop reads only smem.
// Math in f32x2 packed pairs.
// ---------------------------------------------------------------------------
#define CHUNK   4
#define HALO    324                 // 18*18
#define FROW    36                  // padded feature smem row (floats)
#define FCH     (32 * FROW)         // 1152 floats per staged channel
#define NITER   (Cn / CHUNK)        // 16

__global__ __launch_bounds__(256, 4) void diff_kernel(const float* __restrict__ feat,
                                                      float* __restrict__ out) {
    __shared__ __align__(16) float sfeat[2][CHUNK * FCH];  // 36,864 B
    __shared__ float shalo[2][CHUNK * HALO];               // 10,368 B
    __shared__ float sP2[HALO];                            //  1,296 B

    int b   = blockIdx.z;
    int ph0 = blockIdx.y << 4;
    int pw0 = blockIdx.x << 4;
    int tid = threadIdx.x;
    int qx  = tid & 15, qy = tid >> 4;

    const float* fimg = feat + (size_t)b * Cn * CH_STRIDE;
    const float* pimg = g_pooled + (size_t)b * Cn * PCH_STRIDE;
    int sbase = (qy + 1) * 18 + (qx + 1);

    unsigned int sfeat_a = (unsigned int)__cvta_generic_to_shared(&sfeat[0][0]);
    unsigned int shalo_a = (unsigned int)__cvta_generic_to_shared(&shalo[0][0]);

    // ---- per-thread staging constants (computed ONCE) ----
    // halo: thread owns cell0 = tid, and cell1 = tid+256 if tid < 68
    int i0 = tid / 18, j0 = tid - i0 * 18;
    int gofs0 = ((((ph0 - 1 + i0) & 127) << 7) | ((pw0 - 1 + j0) & 127));
    int cell1 = tid + 256;
    int i1 = cell1 / 18, j1 = cell1 - i1 * 18;
    int gofs1 = ((((ph0 - 1 + i1) & 127) << 7) | ((pw0 - 1 + j1) & 127));
    bool has1 = (cell1 < HALO);
    // feature: thread stages row=tid>>3, col4=(tid&7)*4 for each of CHUNK channels
    int frow = tid >> 3;
    int fcol = (tid & 7) << 2;
    const float* fsrc_base = fimg + (size_t)((ph0 << 1) + frow) * Wn + (pw0 << 1) + fcol;
    unsigned int fdst_base = sfeat_a + (unsigned int)(frow * FROW + fcol) * 4;

    // ---- staging: one 4-channel chunk (feature tile + pooled halo) ----
    auto stage = [&](int buf, int cc) {
        unsigned int fd = fdst_base + buf * (CHUNK * FCH * 4);
        const float* fs = fsrc_base + (size_t)cc * CH_STRIDE;
#pragma unroll
        for (int m = 0; m < CHUNK; m++) {
            cp_async16(fd + m * (FCH * 4), fs);
            fs += CH_STRIDE;
        }
        unsigned int hd = shalo_a + buf * (CHUNK * HALO * 4);
        const float* hs = pimg + (size_t)cc * PCH_STRIDE;
#pragma unroll
        for (int c = 0; c < CHUNK; c++) {
            cp_async4(hd + (c * HALO + tid) * 4, hs + gofs0);
            if (has1) cp_async4(hd + (c * HALO + cell1) * 4, hs + gofs1);
            hs += PCH_STRIDE;
        }
        cp_commit();
    };

    u64 z = 0;
    u64 cr01[8], cr23[8];
#pragma unroll
    for (int s = 0; s < 8; s++) { cr01[s] = z; cr23[s] = z; }
    u64 F2_01 = z, F2_23 = z;

    stage(0, 0);

    for (int it = 0; it < NITER; it++) {
        int cur = it & 1;
        if (it + 1 < NITER) { stage(1 - cur, (it + 1) * CHUNK); cp_wait1(); }
        else                { cp_wait0(); }
        __syncthreads();                    // staged chunk visible to all

        const float* hbuf = &shalo[cur][0];
        const float* fbuf = &sfeat[cur][0];

        // ---- fold P2 over the staged halo (thread-owned cells)
        {
            float acc0 = (it == 0) ? 0.f : sP2[tid];
#pragma unroll
            for (int c = 0; c < CHUNK; c++) {
                float v = hbuf[c * HALO + tid];
                acc0 += v * v;
            }
            sP2[tid] = acc0;
            if (has1) {
                float acc1 = (it == 0) ? 0.f : sP2[cell1];
#pragma unroll
                for (int c = 0; c < CHUNK; c++) {
                    float v = hbuf[c * HALO + cell1];
                    acc1 += v * v;
                }
                sP2[cell1] = acc1;
            }
        }

        // ---- quad accumulation (all operands from smem)
#pragma unroll
        for (int c = 0; c < CHUNK; c++) {
            const float* fp = fbuf + c * FCH + (qy << 1) * FROW + (qx << 1);
            u64 f01 = as_u64(*reinterpret_cast<const float2*>(fp));
            u64 f23 = as_u64(*reinterpret_cast<const float2*>(fp + FROW));

            const float* hc = hbuf + c * HALO;
            float ps[8];
            ps[0] = hc[sbase - 19]; ps[1] = hc[sbase - 18]; ps[2] = hc[sbase - 17];
            ps[3] = hc[sbase - 1];                          ps[4] = hc[sbase + 1];
            ps[5] = hc[sbase + 17]; ps[6] = hc[sbase + 18]; ps[7] = hc[sbase + 19];

            fma2(F2_01, f01, f01);
            fma2(F2_23, f23, f23);
#pragma unroll
            for (int s = 0; s < 8; s++) {
                u64 pp = bcast2(ps[s]);
                fma2(cr01[s], f01, pp);
                fma2(cr23[s], f23, pp);
            }
        }
        __syncthreads();                    // all reads done before restaging
    }

    // ---- P2 at the 8 neighbors from the smem tile
    float P2n[8];
    P2n[0] = sP2[sbase - 19]; P2n[1] = sP2[sbase - 18]; P2n[2] = sP2[sbase - 17];
    P2n[3] = sP2[sbase - 1];                             P2n[4] = sP2[sbase + 1];
    P2n[5] = sP2[sbase + 17]; P2n[6] = sP2[sbase + 18]; P2n[7] = sP2[sbase + 19];

    float2 F2p01 = unpack2(F2_01);
    float2 F2p23 = unpack2(F2_23);
    float F2arr[4] = {F2p01.x, F2p01.y, F2p23.x, F2p23.y};

    float res[4] = {-3.4e38f, -3.4e38f, -3.4e38f, -3.4e38f};
#pragma unroll
    for (int s = 0; s < 8; s++) {
        float2 c01 = unpack2(cr01[s]);
        float2 c23 = unpack2(cr23[s]);
        res[0] = fmaxf(res[0], F2arr[0] - 2.f * c01.x + P2n[s]);
        res[1] = fmaxf(res[1], F2arr[1] - 2.f * c01.y + P2n[s]);
        res[2] = fmaxf(res[2], F2arr[2] - 2.f * c23.x + P2n[s]);
        res[3] = fmaxf(res[3], F2arr[3] - 2.f * c23.y + P2n[s]);
    }

    int ph = ph0 + qy, pw = pw0 + qx;
    float* orow = out + (size_t)b * (Hn * Wn) + (ph << 1) * Wn + (pw << 1);
    *reinterpret_cast<float2*>(orow)      = make_float2(res[0], res[1]);
    *reinterpret_cast<float2*>(orow + Wn) = make_float2(res[2], res[3]);
}

// ---------------------------------------------------------------------------
extern "C" void kernel_launch(void* const* d_in, const int* in_sizes, int n_in,
                              void* d_out, int out_size) {
    const float* feat = (const float*)d_in[0];
    float* out = (float*)d_out;
    // dist is fixed at 1 by the problem's setup_inputs (d = 2)

    pool_kernel<<<16384, 256>>>(feat);
    dim3 g(8, 8, Bn);
    diff_kernel<<<g, 256>>>(feat, out);
}